// round 9
// baseline (speedup 1.0000x reference)
#include <cuda_runtime.h>
#include <cuda_fp16.h>

// Problem constants
#define BB   256
#define LL   2048
#define DD   128
#define VV   6000
#define TMAX 48

#define NTHREADS 512
#define NWARPS   16
#define SORT_CAP (LL + TMAX * 8)   // bins padded to x8

// 8-byte vector of 4 halves; plain loads/stores, no type punning anywhere.
struct alignas(8) Half4 { __half2 lo, hi; };

// Pre-scaled fp16 table: g_tab4[v*32 + j] holds elements [4j, 4j+4) of row v,
// where row v = exp(embW[v]) * embX[v][:].  1.5MB __device__ scratch.
__device__ Half4 g_tab4[(size_t)VV * (DD / 4)];

// Kernel 0: build scaled fp16 table. One thread per 4 elements.
__global__ void scale_kernel(const float* __restrict__ embX,
                             const float* __restrict__ embW) {
    int idx = blockIdx.x * blockDim.x + threadIdx.x;   // Half4 index
    if (idx < VV * (DD / 4)) {
        int v = idx >> 5;                               // 32 Half4 per row
        float w = __expf(embW[v]);
        float4 e = reinterpret_cast<const float4*>(embX)[idx];
        Half4 q;
        q.lo = __floats2half2_rn(e.x * w, e.y * w);
        q.hi = __floats2half2_rn(e.z * w, e.w * w);
        g_tab4[idx] = q;
    }
}

// Kernel 1: one CTA per batch row.
//   Phase 0: atomic-free counting sort into 48 bins (match_any histograms,
//            hierarchical cursors; bins padded to x8 with id=0 == zero row).
//   Phase 1: rank-balanced warp-per-bin fp32 accumulation from fp16 table.
__global__ void __launch_bounds__(NTHREADS, 2)
embedder_kernel(const float* __restrict__ X, float* __restrict__ out) {
    const int b    = blockIdx.x;
    const int tid  = threadIdx.x;
    const int warp = tid >> 5;
    const int lane = tid & 31;

    __shared__ __align__(16) int s_sorted[SORT_CAP];   // bin-sorted ids (pad=0)
    __shared__ int s_meta[LL];                          // packed (bin<<13)|id
    __shared__ int s_whist[NWARPS * TMAX];
    __shared__ int s_wcur[NWARPS * TMAX];
    __shared__ int s_hist[TMAX];
    __shared__ int s_offP[TMAX + 1];
    __shared__ int s_assign[TMAX];

    #pragma unroll 1
    for (int i = tid; i < SORT_CAP; i += NTHREADS) s_sorted[i] = 0;
    #pragma unroll 1
    for (int i = tid; i < NWARPS * TMAX; i += NTHREADS) s_whist[i] = 0;
    __syncthreads();

    // ---------- Phase 0a: load meta + warp-private histogram ----------
    const float2* __restrict__ Xb =
        reinterpret_cast<const float2*>(X) + (size_t)b * LL;
    #pragma unroll
    for (int it = 0; it < LL / NTHREADS; ++it) {
        int t = it * NTHREADS + tid;
        float2 m = Xb[t];                    // m.x = T (>=0), m.y = id
        int bin = (int)m.x;                  // trunc == floor (T >= 0)
        bin = min(max(bin, 0), TMAX - 1);
        int id = (int)m.y;                   // 1..5999 exact in fp32
        s_meta[t] = (bin << 13) | id;
        unsigned g = __match_any_sync(0xffffffffu, bin);
        if ((int)(__ffs(g) - 1) == lane)     // leader: plain RMW, race-free
            s_whist[warp * TMAX + bin] += __popc(g);
    }
    __syncthreads();

    // ---------- Phase 0b: totals ----------
    if (tid < TMAX) {
        int c = 0;
        #pragma unroll
        for (int w = 0; w < NWARPS; w++) c += s_whist[w * TMAX + tid];
        s_hist[tid] = c;
    }
    __syncthreads();

    // Rank bins by count + snake-partition across 16 warps.
    if (tid < TMAX) {
        int c = s_hist[tid];
        int r = 0;
        #pragma unroll 8
        for (int j = 0; j < TMAX; j++) {
            int cj = s_hist[j];
            r += (cj > c) || (cj == c && j < tid);
        }
        int w, slot;
        if (r < NWARPS)          { w = r;                  slot = 0; }
        else if (r < 2 * NWARPS) { w = 2 * NWARPS - 1 - r; slot = 1; }
        else                     { w = r - 2 * NWARPS;     slot = 2; }
        s_assign[w * 3 + slot] = tid;
    }
    // Padded (x8) exclusive prefix.
    if (tid == 0) {
        int acc = 0;
        #pragma unroll
        for (int i = 0; i < TMAX; i++) {
            s_offP[i] = acc;
            acc += (s_hist[i] + 7) & ~7;     // pad ids are 0 == zero row
        }
        s_offP[TMAX] = acc;
    }
    __syncthreads();

    // Per-(warp,bin) scatter cursors.
    #pragma unroll 1
    for (int i = tid; i < NWARPS * TMAX; i += NTHREADS) {
        int w = i / TMAX, bin = i - w * TMAX;
        int c = s_offP[bin];
        for (int w2 = 0; w2 < w; w2++) c += s_whist[w2 * TMAX + bin];
        s_wcur[i] = c;
    }
    __syncthreads();

    // ---------- Phase 0c: atomic-free scatter (same order as 0a) ----------
    #pragma unroll
    for (int it = 0; it < LL / NTHREADS; ++it) {
        int t = it * NTHREADS + tid;
        int m = s_meta[t];
        int bin = m >> 13;
        unsigned g = __match_any_sync(0xffffffffu, bin);
        int leader = __ffs(g) - 1;
        int rank = __popc(g & ((1u << lane) - 1u));
        int base = 0;
        if (lane == leader) {
            base = s_wcur[warp * TMAX + bin];
            s_wcur[warp * TMAX + bin] = base + __popc(g);
        }
        base = __shfl_sync(0xffffffffu, base, leader);
        s_sorted[base + rank] = m & 8191;
    }
    __syncthreads();

    // ---------- Phase 1: warp-per-bin gather, fp16 rows, fp32 accumulate ----------
    const Half4* __restrict__ tab = g_tab4;
    #pragma unroll 1
    for (int slot = 0; slot < 3; ++slot) {
        const int bin = s_assign[warp * 3 + slot];
        const int beg = s_offP[bin];
        const int end = s_offP[bin + 1];     // (end-beg) % 8 == 0
        const int cnt = s_hist[bin];

        float ax = 0.f, ay = 0.f, az = 0.f, aw = 0.f;

        #pragma unroll 1
        for (int i = beg; i < end; i += 8) {
            int4 ia = *reinterpret_cast<const int4*>(s_sorted + i);      // 16B-aligned
            int4 ib = *reinterpret_cast<const int4*>(s_sorted + i + 4);
            Half4 q0 = tab[ia.x * 32 + lane];   // 8 outstanding LDG.64
            Half4 q1 = tab[ia.y * 32 + lane];
            Half4 q2 = tab[ia.z * 32 + lane];
            Half4 q3 = tab[ia.w * 32 + lane];
            Half4 q4 = tab[ib.x * 32 + lane];
            Half4 q5 = tab[ib.y * 32 + lane];
            Half4 q6 = tab[ib.z * 32 + lane];
            Half4 q7 = tab[ib.w * 32 + lane];

            float2 f;
            f = __half22float2(q0.lo); ax += f.x; ay += f.y;
            f = __half22float2(q0.hi); az += f.x; aw += f.y;
            f = __half22float2(q1.lo); ax += f.x; ay += f.y;
            f = __half22float2(q1.hi); az += f.x; aw += f.y;
            f = __half22float2(q2.lo); ax += f.x; ay += f.y;
            f = __half22float2(q2.hi); az += f.x; aw += f.y;
            f = __half22float2(q3.lo); ax += f.x; ay += f.y;
            f = __half22float2(q3.hi); az += f.x; aw += f.y;
            f = __half22float2(q4.lo); ax += f.x; ay += f.y;
            f = __half22float2(q4.hi); az += f.x; aw += f.y;
            f = __half22float2(q5.lo); ax += f.x; ay += f.y;
            f = __half22float2(q5.hi); az += f.x; aw += f.y;
            f = __half22float2(q6.lo); ax += f.x; ay += f.y;
            f = __half22float2(q6.hi); az += f.x; aw += f.y;
            f = __half22float2(q7.lo); ax += f.x; ay += f.y;
            f = __half22float2(q7.hi); az += f.x; aw += f.y;
        }

        const float inv = 1.0f / ((float)cnt + 1e-6f);
        float4 o = make_float4(ax * inv, ay * inv, az * inv, aw * inv);
        reinterpret_cast<float4*>(out + ((size_t)b * TMAX + bin) * DD)[lane] = o;
    }
}

extern "C" void kernel_launch(void* const* d_in, const int* in_sizes, int n_in,
                              void* d_out, int out_size) {
    const float* X    = (const float*)d_in[0];   // [B, L, 2] fp32
    const float* embX = (const float*)d_in[1];   // [V, D] fp32
    const float* embW = (const float*)d_in[2];   // [V+1, 1] fp32
    float* out = (float*)d_out;                  // [B, TMAX, D] fp32

    scale_kernel<<<(VV * (DD / 4) + 255) / 256, 256>>>(embX, embW);
    embedder_kernel<<<BB, NTHREADS>>>(X, out);
}

// round 10
// speedup vs baseline: 1.1384x; 1.1384x over previous
#include <cuda_runtime.h>
#include <cuda_fp16.h>

// Problem constants
#define BB   256
#define LL   2048
#define DD   128
#define VV   6000
#define TMAX 48

#define LH       1024              // tokens per CTA (half a batch row)
#define NT       384               // threads per CTA
#define NW       12                // warps per CTA
#define NCTA     (BB * 2)          // 512 CTAs
#define SORT_CAP (LH + TMAX * 8)   // bins padded to x8

// Pre-scaled fp32 table: g_scaled[v][d] = exp(embW[v]) * embX[v][d]. 3MB.
__device__ float g_scaled[(size_t)VV * DD];
// Per-CTA partial sums [512][48][128] (12.6MB) + counts [512][48].
__device__ float g_part[(size_t)NCTA * TMAX * DD];
__device__ float g_pcnt[NCTA * TMAX];

// Kernel 0: build scaled table. One thread per float4.
__global__ void scale_kernel(const float* __restrict__ embX,
                             const float* __restrict__ embW) {
    int idx = blockIdx.x * blockDim.x + threadIdx.x;
    if (idx < VV * (DD / 4)) {
        int v = idx >> 5;                               // 32 float4 per row
        float w = __expf(embW[v]);
        float4 e = reinterpret_cast<const float4*>(embX)[idx];
        reinterpret_cast<float4*>(g_scaled)[idx] =
            make_float4(e.x * w, e.y * w, e.z * w, e.w * w);
    }
}

// Kernel 1: one CTA per half batch row. Atomic-free counting sort of 1024
// tokens into 48 bins, then rank-balanced warp-per-bin (4 bins/warp) fp32
// register accumulation; plain coalesced partial-sum writes (no atomics).
__global__ void __launch_bounds__(NT, 4)
partial_kernel(const float* __restrict__ X) {
    const int cta  = blockIdx.x;
    const int b    = cta >> 1;
    const int h    = cta & 1;
    const int tid  = threadIdx.x;
    const int warp = tid >> 5;
    const int lane = tid & 31;

    __shared__ __align__(16) int s_sorted[SORT_CAP];
    __shared__ int s_meta[LH];                  // packed (bin<<13)|id
    __shared__ int s_whist[NW * TMAX];
    __shared__ int s_wcur[NW * TMAX];
    __shared__ int s_hist[TMAX];
    __shared__ int s_offP[TMAX + 1];
    __shared__ int s_assign[TMAX];              // (warp,slot) -> bin

    #pragma unroll 1
    for (int i = tid; i < SORT_CAP; i += NT) s_sorted[i] = 0;
    #pragma unroll 1
    for (int i = tid; i < NW * TMAX; i += NT) s_whist[i] = 0;
    __syncthreads();

    // ---------- Phase 0a: meta load + warp-private histogram ----------
    // Trip counts are warp-uniform (1024 = 2*384 + 256; boundary tid=256 is
    // warp-aligned), so __match_any_sync inside is safe.
    const float2* __restrict__ Xb =
        reinterpret_cast<const float2*>(X) + (size_t)b * LL + h * LH;
    #pragma unroll 1
    for (int t = tid; t < LH; t += NT) {
        float2 m = Xb[t];                       // m.x = T (>=0), m.y = id
        int bin = (int)m.x;                     // trunc == floor for T >= 0
        bin = min(max(bin, 0), TMAX - 1);
        int id = (int)m.y;                      // 1..5999 exact in fp32
        s_meta[t] = (bin << 13) | id;
        unsigned g = __match_any_sync(0xffffffffu, bin);
        if ((int)(__ffs(g) - 1) == lane)        // leader: plain RMW, race-free
            s_whist[warp * TMAX + bin] += __popc(g);
    }
    __syncthreads();

    // ---------- Phase 0b: totals ----------
    if (tid < TMAX) {
        int c = 0;
        #pragma unroll
        for (int w = 0; w < NW; w++) c += s_whist[w * TMAX + tid];
        s_hist[tid] = c;
    }
    __syncthreads();

    // Rank bins by count, snake-partition into 12 warps x 4 slots.
    if (tid < TMAX) {
        int c = s_hist[tid];
        int r = 0;
        #pragma unroll 8
        for (int j = 0; j < TMAX; j++) {
            int cj = s_hist[j];
            r += (cj > c) || (cj == c && j < tid);
        }
        int s = r / NW, i = r - s * NW;
        int w = (s & 1) ? (NW - 1 - i) : i;
        s_assign[w * 4 + s] = tid;
    }
    // Padded (x8) exclusive prefix (pad ids = 0 == zero row).
    if (tid == 0) {
        int acc = 0;
        #pragma unroll
        for (int i = 0; i < TMAX; i++) {
            s_offP[i] = acc;
            acc += (s_hist[i] + 7) & ~7;
        }
        s_offP[TMAX] = acc;
    }
    __syncthreads();

    // Per-(warp,bin) scatter cursors.
    #pragma unroll 1
    for (int i = tid; i < NW * TMAX; i += NT) {
        int w = i / TMAX, bin = i - w * TMAX;
        int c = s_offP[bin];
        for (int w2 = 0; w2 < w; w2++) c += s_whist[w2 * TMAX + bin];
        s_wcur[i] = c;
    }
    __syncthreads();

    // ---------- Phase 0c: atomic-free scatter (same order as 0a) ----------
    #pragma unroll 1
    for (int t = tid; t < LH; t += NT) {
        int m = s_meta[t];
        int bin = m >> 13;
        unsigned g = __match_any_sync(0xffffffffu, bin);
        int leader = __ffs(g) - 1;
        int rank = __popc(g & ((1u << lane) - 1u));
        int base = 0;
        if (lane == leader) {
            base = s_wcur[warp * TMAX + bin];
            s_wcur[warp * TMAX + bin] = base + __popc(g);
        }
        base = __shfl_sync(0xffffffffu, base, leader);
        s_sorted[base + rank] = m & 8191;
    }
    __syncthreads();

    // ---------- Phase 1: warp-per-bin fp32 gather-accumulate ----------
    const float4* __restrict__ tab = reinterpret_cast<const float4*>(g_scaled);
    float4* __restrict__ part4 = reinterpret_cast<float4*>(g_part);
    #pragma unroll 1
    for (int slot = 0; slot < 4; ++slot) {
        const int bin = s_assign[warp * 4 + slot];
        const int beg = s_offP[bin];
        const int end = s_offP[bin + 1];        // (end-beg) % 8 == 0
        const int cnt = s_hist[bin];

        float ax = 0.f, ay = 0.f, az = 0.f, aw = 0.f;

        #pragma unroll 1
        for (int i = beg; i < end; i += 4) {
            int4 ids = *reinterpret_cast<const int4*>(s_sorted + i);
            float4 e0 = tab[ids.x * 32 + lane];
            float4 e1 = tab[ids.y * 32 + lane];
            float4 e2 = tab[ids.z * 32 + lane];
            float4 e3 = tab[ids.w * 32 + lane];
            ax += (e0.x + e1.x) + (e2.x + e3.x);
            ay += (e0.y + e1.y) + (e2.y + e3.y);
            az += (e0.z + e1.z) + (e2.z + e3.z);
            aw += (e0.w + e1.w) + (e2.w + e3.w);
        }

        part4[((size_t)cta * TMAX + bin) * 32 + lane] =
            make_float4(ax, ay, az, aw);
        if (lane == 0) g_pcnt[cta * TMAX + bin] = (float)cnt;
    }
}

// Kernel 2: merge the two half-row partials and normalize. ~19MB streamed.
__global__ void merge_kernel(float* __restrict__ out) {
    int idx = blockIdx.x * blockDim.x + threadIdx.x;   // float4 index into out
    if (idx < BB * TMAX * (DD / 4)) {
        int l   = idx & 31;
        int row = idx >> 5;                 // b*TMAX + bin
        int b   = row / TMAX;
        int bin = row - b * TMAX;
        const float4* gp = reinterpret_cast<const float4*>(g_part);
        float4 p0 = gp[((size_t)(2 * b)     * TMAX + bin) * 32 + l];
        float4 p1 = gp[((size_t)(2 * b + 1) * TMAX + bin) * 32 + l];
        float c = g_pcnt[(2 * b) * TMAX + bin] + g_pcnt[(2 * b + 1) * TMAX + bin];
        float inv = 1.0f / (c + 1e-6f);
        reinterpret_cast<float4*>(out)[idx] =
            make_float4((p0.x + p1.x) * inv, (p0.y + p1.y) * inv,
                        (p0.z + p1.z) * inv, (p0.w + p1.w) * inv);
    }
}

extern "C" void kernel_launch(void* const* d_in, const int* in_sizes, int n_in,
                              void* d_out, int out_size) {
    const float* X    = (const float*)d_in[0];   // [B, L, 2] fp32
    const float* embX = (const float*)d_in[1];   // [V, D] fp32
    const float* embW = (const float*)d_in[2];   // [V+1, 1] fp32
    float* out = (float*)d_out;                  // [B, TMAX, D] fp32

    scale_kernel<<<(VV * (DD / 4) + 255) / 256, 256>>>(embX, embW);
    partial_kernel<<<NCTA, NT>>>(X);
    merge_kernel<<<(BB * TMAX * (DD / 4) + 255) / 256, 256>>>(out);
}